// round 2
// baseline (speedup 1.0000x reference)
#include <cuda_runtime.h>

#define K_DIM   128
#define NBS     256          // bs = batch_size * clips
#define QK      131072       // queue size
#define LDOUT   (QK + 1)     // out row stride
#define BATCH   64           // videos
#define BM      128
#define BN      128
#define BK      32
#define PAD     5

__device__ double g_sumZ;
__device__ float  g_rowsum[NBS];
__device__ float  g_invZ;

static __constant__ float INV_T = 1.0f / 0.07f;

__global__ void init_kernel() {
    int t = threadIdx.x;
    if (t == 0) g_sumZ = 0.0;
    if (t < NBS) g_rowsum[t] = 0.0f;
}

// 128x128 tile, 256 threads, each thread computes 16 rows x 4 cols.
// tn = tid & 31 (col group), tm = tid >> 5 (row group). Each warp (fixed tm)
// owns exactly rows [tm*16, tm*16+16) of the tile -> warp-local row reduce.
__global__ __launch_bounds__(256, 2)
void gemm_exp_kernel(const float* __restrict__ q,
                     const float* __restrict__ mem,
                     float* __restrict__ out) {
    __shared__ float As[BK][BM + PAD];
    __shared__ float Bs[BK][BN + PAD];
    __shared__ float wsum[8];

    const int tid = threadIdx.x;
    const int m0 = blockIdx.y * BM;
    const int n0 = blockIdx.x * BN;
    const int tn = tid & 31;
    const int tm = tid >> 5;

    float acc[16][4];
#pragma unroll
    for (int i = 0; i < 16; i++)
#pragma unroll
        for (int j = 0; j < 4; j++) acc[i][j] = 0.0f;

    for (int k0 = 0; k0 < K_DIM; k0 += BK) {
        // Load 128x32 A and B chunks: 16 elements per thread each, coalesced on k.
#pragma unroll
        for (int t = 0; t < 16; t++) {
            int idx = t * 256 + tid;        // 0..4095
            int m  = idx >> 5;
            int kk = idx & 31;
            As[kk][m] = q[(size_t)(m0 + m) * K_DIM + k0 + kk];
            Bs[kk][m] = mem[(size_t)(n0 + m) * K_DIM + k0 + kk];
        }
        __syncthreads();
#pragma unroll
        for (int kk = 0; kk < BK; kk++) {
            float a[16], b[4];
#pragma unroll
            for (int i = 0; i < 16; i++) a[i] = As[kk][tm * 16 + i];
#pragma unroll
            for (int j = 0; j < 4; j++)  b[j] = Bs[kk][tn + 32 * j];
#pragma unroll
            for (int i = 0; i < 16; i++)
#pragma unroll
                for (int j = 0; j < 4; j++)
                    acc[i][j] = fmaf(a[i], b[j], acc[i][j]);
        }
        __syncthreads();
    }

    // exp, store (cols are 1 + n0 + tn + 32*j -> warp writes 32 consecutive floats per j)
    float tsum = 0.0f;
    float rpart[16];
#pragma unroll
    for (int i = 0; i < 16; i++) {
        const size_t rowbase = (size_t)(m0 + tm * 16 + i) * LDOUT + 1 + n0;
        float rs = 0.0f;
#pragma unroll
        for (int j = 0; j < 4; j++) {
            float e = expf(acc[i][j] * INV_T);
            out[rowbase + tn + 32 * j] = e;
            rs += e;
        }
        rpart[i] = rs;
        tsum += rs;
    }

    // Per-row reduce across the warp's 32 lanes (each warp owns its 16 rows fully).
#pragma unroll
    for (int i = 0; i < 16; i++) {
        float v = rpart[i];
#pragma unroll
        for (int o = 16; o > 0; o >>= 1) v += __shfl_down_sync(0xffffffffu, v, o);
        if (tn == 0) atomicAdd(&g_rowsum[m0 + tm * 16 + i], v);
    }

    // Block sum for Z (double atomic, 2048 total)
#pragma unroll
    for (int o = 16; o > 0; o >>= 1) tsum += __shfl_down_sync(0xffffffffu, tsum, o);
    if (tn == 0) wsum[tm] = tsum;
    __syncthreads();
    if (tid == 0) {
        float s = 0.0f;
#pragma unroll
        for (int w = 0; w < 8; w++) s += wsum[w];
        atomicAdd(&g_sumZ, (double)s);
    }
}

// l_pos: row r's positives are the other 3 clips of video v = r % 64:
// rows {v, v+64, v+128, v+192} \ {r}. l_pos = mean of the 3 dots with q[r].
__global__ void lpos_kernel(const float* __restrict__ q,
                            const float* __restrict__ k,
                            float* __restrict__ out) {
    __shared__ float ws[8];
    const int r = threadIdx.x;       // 256 threads, 1 block
    const int v = r & 63;
    float acc = 0.0f;
#pragma unroll
    for (int c = 0; c < 4; c++) {
        int p = v + c * 64;
        if (p == r) continue;
        float s = 0.0f;
#pragma unroll 8
        for (int d = 0; d < K_DIM; d++)
            s = fmaf(q[(size_t)r * K_DIM + d], k[(size_t)p * K_DIM + d], s);
        acc += s;
    }
    float e = expf((acc * (1.0f / 3.0f)) * INV_T);
    out[(size_t)r * LDOUT] = e;
    atomicAdd(&g_rowsum[r], e);

    float t = e;
#pragma unroll
    for (int o = 16; o > 0; o >>= 1) t += __shfl_down_sync(0xffffffffu, t, o);
    if ((r & 31) == 0) ws[r >> 5] = t;
    __syncthreads();
    if (r == 0) {
        float s = 0.0f;
#pragma unroll
        for (int w = 0; w < 8; w++) s += ws[w];
        atomicAdd(&g_sumZ, (double)s);
    }
}

// probs from UNscaled values (Z cancels in the ratio), plus compute invZ.
__global__ void finalize_kernel(const float* __restrict__ out,
                                float* __restrict__ probs_out) {
    __shared__ float ws[8];
    const int r = threadIdx.x;       // 256 threads, 1 block
    float term = out[(size_t)r * LDOUT] / g_rowsum[r];
#pragma unroll
    for (int o = 16; o > 0; o >>= 1) term += __shfl_down_sync(0xffffffffu, term, o);
    if ((r & 31) == 0) ws[r >> 5] = term;
    __syncthreads();
    if (r == 0) {
        float s = 0.0f;
#pragma unroll
        for (int w = 0; w < 8; w++) s += ws[w];
        probs_out[0] = s / (float)NBS;
        double Z = g_sumZ / ((double)NBS * (double)LDOUT) * 1.0e6;
        g_invZ = (float)(1.0 / Z);
    }
}

// out *= 1/Z over the whole [bs, 1+K] block (flat count divisible by 4,
// and the `out` base pointer == d_out which is 256B-aligned -> float4 OK).
__global__ void scale_kernel(float4* __restrict__ out) {
    const size_t n4 = (size_t)NBS * LDOUT / 4;
    size_t i = (size_t)blockIdx.x * blockDim.x + threadIdx.x;
    const float inv = g_invZ;
    if (i < n4) {
        float4 v = out[i];
        v.x *= inv; v.y *= inv; v.z *= inv; v.w *= inv;
        out[i] = v;
    }
}

// new_memory: copy, with rows 0..63 replaced by mean of video's 4 clip keys.
// NOTE: newmem base is only 4-byte aligned (it sits after the odd-sized
// [out|probs] block), so all STORES are scalar. Loads from mem/k (aligned
// input buffers) stay vectorized.
__global__ void mem_kernel(const float* __restrict__ mem,
                           const float* __restrict__ k,
                           float* __restrict__ newmem) {
    const size_t n4 = (size_t)QK * K_DIM / 4;   // groups of 4 floats
    size_t i4 = (size_t)blockIdx.x * blockDim.x + threadIdx.x;
    if (i4 >= n4) return;
    int row = (int)(i4 >> 5);            // 32 groups per 128-float row
    float4 v;
    if (row < BATCH) {
        int d4 = (int)(i4 & 31);
        const float4* k4 = (const float4*)k;
        float4 a = k4[(size_t)row * 32 + d4];
        float4 b = k4[(size_t)(row + 64) * 32 + d4];
        float4 c = k4[(size_t)(row + 128) * 32 + d4];
        float4 d = k4[(size_t)(row + 192) * 32 + d4];
        v.x = 0.25f * (a.x + b.x + c.x + d.x);
        v.y = 0.25f * (a.y + b.y + c.y + d.y);
        v.z = 0.25f * (a.z + b.z + c.z + d.z);
        v.w = 0.25f * (a.w + b.w + c.w + d.w);
    } else {
        v = ((const float4*)mem)[i4];
    }
    float* o = newmem + i4 * 4;          // scalar stores: base only 4B-aligned
    o[0] = v.x; o[1] = v.y; o[2] = v.z; o[3] = v.w;
}

extern "C" void kernel_launch(void* const* d_in, const int* in_sizes, int n_in,
                              void* d_out, int out_size) {
    const float* q   = (const float*)d_in[0];
    const float* k   = (const float*)d_in[1];
    const float* mem = (const float*)d_in[2];
    // d_in[3] = i (unused: out_ids = arange(64) % QK regardless)
    float* out = (float*)d_out;

    // Layout: [out 256*131073][probs 1][new_memory 131072*128]
    size_t mem_off = (size_t)out_size - (size_t)QK * K_DIM;
    float* newmem = out + mem_off;
    float* probs  = out + (mem_off - 1);

    init_kernel<<<1, 256>>>();

    dim3 grid(QK / BN, NBS / BM);
    gemm_exp_kernel<<<grid, 256>>>(q, mem, out);

    lpos_kernel<<<1, 256>>>(q, k, out);
    finalize_kernel<<<1, 256>>>(out, probs);

    size_t n4 = (size_t)NBS * LDOUT / 4;
    scale_kernel<<<(unsigned)((n4 + 255) / 256), 256>>>((float4*)out);

    size_t m4 = (size_t)QK * K_DIM / 4;
    mem_kernel<<<(unsigned)((m4 + 255) / 256), 256>>>(mem, k, newmem);
}

// round 4
// speedup vs baseline: 1.2952x; 1.2952x over previous
#include <cuda_runtime.h>
#include <cuda_bf16.h>
#include <cstdint>

#define K_DIM   128
#define NBS     256
#define QK      131072
#define LDOUT   (QK + 1)
#define BATCH   64
#define SSTRIDE 136                      // bf16 elems per smem row (padded)

__device__ double g_sumZ;
__device__ double g_Zpart[2048];
__device__ float  g_rowsum[NBS];
__device__ float  g_invZ;
__device__ __align__(16) __nv_bfloat16 g_qhi[NBS * K_DIM];
__device__ __align__(16) __nv_bfloat16 g_qlo[NBS * K_DIM];

static __constant__ float INV_T = 1.0f / 0.07f;

__global__ void init_kernel(const float* __restrict__ q) {
    int t = blockIdx.x * blockDim.x + threadIdx.x;   // 128 x 256 = 32768
    if (t == 0) g_sumZ = 0.0;
    if (t < NBS) g_rowsum[t] = 0.0f;
    float v = q[t];
    __nv_bfloat16 hi = __float2bfloat16(v);
    __nv_bfloat16 lo = __float2bfloat16(v - __bfloat162float(hi));
    g_qhi[t] = hi;
    g_qlo[t] = lo;
}

__device__ __forceinline__ uint32_t pack2(__nv_bfloat16 a, __nv_bfloat16 b) {
    return (uint32_t)__bfloat16_as_ushort(a) | ((uint32_t)__bfloat16_as_ushort(b) << 16);
}

__device__ __forceinline__ uint32_t lds_b32(const __nv_bfloat16* base, int r, int c) {
    return *reinterpret_cast<const uint32_t*>(base + r * SSTRIDE + c);
}

__device__ __forceinline__ void mma_bf16(float* c, const uint32_t* a, const uint32_t* b) {
    asm volatile(
        "mma.sync.aligned.m16n8k16.row.col.f32.bf16.bf16.f32 "
        "{%0,%1,%2,%3}, {%4,%5,%6,%7}, {%8,%9}, {%0,%1,%2,%3};"
        : "+f"(c[0]), "+f"(c[1]), "+f"(c[2]), "+f"(c[3])
        : "r"(a[0]), "r"(a[1]), "r"(a[2]), "r"(a[3]), "r"(b[0]), "r"(b[1]));
}

// grid (2, 1024): blockIdx.x = M half (128 rows), blockIdx.y = N tile (128 cols).
// Adjacent CTAs share the same B tile -> second one hits L2.
// 8 warps: wm = wid&3 (M 32-row band), wn = wid>>2 (N 64-col band).
#define SM_TILE (128 * SSTRIDE)          // bf16 elems per operand tile
#define SMEM_BYTES (4 * SM_TILE * 2)     // A_hi A_lo B_hi B_lo

__global__ __launch_bounds__(256, 1)
void gemm_exp_kernel(const float* __restrict__ mem, float* __restrict__ out) {
    extern __shared__ __align__(16) char smem_raw[];
    __nv_bfloat16* As_hi = reinterpret_cast<__nv_bfloat16*>(smem_raw);
    __nv_bfloat16* As_lo = As_hi + SM_TILE;
    __nv_bfloat16* Bs_hi = As_lo + SM_TILE;
    __nv_bfloat16* Bs_lo = Bs_hi + SM_TILE;

    const int tid = threadIdx.x;
    const int wid = tid >> 5;
    const int lid = tid & 31;
    const int m0 = blockIdx.x * 128;
    const int n0 = blockIdx.y * 128;
    const int wm = wid & 3;
    const int wn = wid >> 2;

    // ---- load A (precomputed hi/lo) + convert B (fp32 -> hi/lo bf16) ----
    {
        const uint4* qhi4 = reinterpret_cast<const uint4*>(g_qhi);
        const uint4* qlo4 = reinterpret_cast<const uint4*>(g_qlo);
        const float4* m4 = reinterpret_cast<const float4*>(mem);
#pragma unroll
        for (int it = 0; it < 8; it++) {
            int chunk = it * 256 + tid;      // 0..2047
            int r  = chunk >> 4;
            int c8 = chunk & 15;
            int c  = c8 * 8;
            int off = r * SSTRIDE + c;       // 16B-aligned (SSTRIDE*2=272=17*16)
            *reinterpret_cast<uint4*>(As_hi + off) = qhi4[(m0 + r) * 16 + c8];
            *reinterpret_cast<uint4*>(As_lo + off) = qlo4[(m0 + r) * 16 + c8];
            size_t bidx = ((size_t)(n0 + r) * K_DIM + c) >> 2;
            float4 f0 = m4[bidx];
            float4 f1 = m4[bidx + 1];
            float f[8] = {f0.x, f0.y, f0.z, f0.w, f1.x, f1.y, f1.z, f1.w};
            __nv_bfloat16 hi[8], lo[8];
#pragma unroll
            for (int j = 0; j < 8; j++) {
                hi[j] = __float2bfloat16(f[j]);
                lo[j] = __float2bfloat16(f[j] - __bfloat162float(hi[j]));
            }
            uint4 vh, vl;
            vh.x = pack2(hi[0], hi[1]); vh.y = pack2(hi[2], hi[3]);
            vh.z = pack2(hi[4], hi[5]); vh.w = pack2(hi[6], hi[7]);
            vl.x = pack2(lo[0], lo[1]); vl.y = pack2(lo[2], lo[3]);
            vl.z = pack2(lo[4], lo[5]); vl.w = pack2(lo[6], lo[7]);
            *reinterpret_cast<uint4*>(Bs_hi + off) = vh;
            *reinterpret_cast<uint4*>(Bs_lo + off) = vl;
        }
    }
    __syncthreads();

    // ---- mainloop ----
    float acc[2][8][4];
#pragma unroll
    for (int mt = 0; mt < 2; mt++)
#pragma unroll
        for (int nt = 0; nt < 8; nt++)
#pragma unroll
            for (int j = 0; j < 4; j++) acc[mt][nt][j] = 0.0f;

    const int ar = lid >> 2;                 // fragment row within 8
    const int akc = (lid & 3) * 2;           // fragment k pair

    // pass 1: B_hi x (A_hi + A_lo)  -> hi*hi + lo*hi
#pragma unroll
    for (int ks = 0; ks < 8; ks++) {
        const int k0 = ks * 16;
        uint32_t ah[2][4], al[2][4], bf[8][2];
#pragma unroll
        for (int mt = 0; mt < 2; mt++) {
            int rb = wm * 32 + mt * 16 + ar;
            ah[mt][0] = lds_b32(As_hi, rb,     k0 + akc);
            ah[mt][1] = lds_b32(As_hi, rb + 8, k0 + akc);
            ah[mt][2] = lds_b32(As_hi, rb,     k0 + akc + 8);
            ah[mt][3] = lds_b32(As_hi, rb + 8, k0 + akc + 8);
            al[mt][0] = lds_b32(As_lo, rb,     k0 + akc);
            al[mt][1] = lds_b32(As_lo, rb + 8, k0 + akc);
            al[mt][2] = lds_b32(As_lo, rb,     k0 + akc + 8);
            al[mt][3] = lds_b32(As_lo, rb + 8, k0 + akc + 8);
        }
#pragma unroll
        for (int nt = 0; nt < 8; nt++) {
            int nb = wn * 64 + nt * 8 + ar;
            bf[nt][0] = lds_b32(Bs_hi, nb, k0 + akc);
            bf[nt][1] = lds_b32(Bs_hi, nb, k0 + akc + 8);
        }
#pragma unroll
        for (int mt = 0; mt < 2; mt++)
#pragma unroll
            for (int nt = 0; nt < 8; nt++) {
                mma_bf16(acc[mt][nt], ah[mt], bf[nt]);
                mma_bf16(acc[mt][nt], al[mt], bf[nt]);
            }
    }
    // pass 2: A_hi x B_lo -> hi*lo
#pragma unroll
    for (int ks = 0; ks < 8; ks++) {
        const int k0 = ks * 16;
        uint32_t ah[2][4], bf[8][2];
#pragma unroll
        for (int mt = 0; mt < 2; mt++) {
            int rb = wm * 32 + mt * 16 + ar;
            ah[mt][0] = lds_b32(As_hi, rb,     k0 + akc);
            ah[mt][1] = lds_b32(As_hi, rb + 8, k0 + akc);
            ah[mt][2] = lds_b32(As_hi, rb,     k0 + akc + 8);
            ah[mt][3] = lds_b32(As_hi, rb + 8, k0 + akc + 8);
        }
#pragma unroll
        for (int nt = 0; nt < 8; nt++) {
            int nb = wn * 64 + nt * 8 + ar;
            bf[nt][0] = lds_b32(Bs_lo, nb, k0 + akc);
            bf[nt][1] = lds_b32(Bs_lo, nb, k0 + akc + 8);
        }
#pragma unroll
        for (int mt = 0; mt < 2; mt++)
#pragma unroll
            for (int nt = 0; nt < 8; nt++)
                mma_bf16(acc[mt][nt], ah[mt], bf[nt]);
    }

    // ---- epilogue: exp, store, row sums, Z partial ----
    float tsum = 0.0f;
#pragma unroll
    for (int mt = 0; mt < 2; mt++) {
        const int row0 = m0 + wm * 32 + mt * 16 + ar;
        float rs0 = 0.0f, rs1 = 0.0f;
#pragma unroll
        for (int nt = 0; nt < 8; nt++) {
            const size_t col = (size_t)(1 + n0 + wn * 64 + nt * 8 + (lid & 3) * 2);
            float e00 = __expf(acc[mt][nt][0] * INV_T);
            float e01 = __expf(acc[mt][nt][1] * INV_T);
            float e10 = __expf(acc[mt][nt][2] * INV_T);
            float e11 = __expf(acc[mt][nt][3] * INV_T);
            out[(size_t)row0 * LDOUT + col]           = e00;
            out[(size_t)row0 * LDOUT + col + 1]       = e01;
            out[(size_t)(row0 + 8) * LDOUT + col]     = e10;
            out[(size_t)(row0 + 8) * LDOUT + col + 1] = e11;
            rs0 += e00 + e01;
            rs1 += e10 + e11;
        }
        tsum += rs0 + rs1;
        // quad reduce (lanes sharing a row are lid&~3 .. +3)
        rs0 += __shfl_xor_sync(0xffffffffu, rs0, 1);
        rs0 += __shfl_xor_sync(0xffffffffu, rs0, 2);
        rs1 += __shfl_xor_sync(0xffffffffu, rs1, 1);
        rs1 += __shfl_xor_sync(0xffffffffu, rs1, 2);
        if ((lid & 3) == 0) {
            atomicAdd(&g_rowsum[row0], rs0);
            atomicAdd(&g_rowsum[row0 + 8], rs1);
        }
    }

    __shared__ float zw[8];
#pragma unroll
    for (int o = 16; o > 0; o >>= 1) tsum += __shfl_down_sync(0xffffffffu, tsum, o);
    if (lid == 0) zw[wid] = tsum;
    __syncthreads();
    if (tid == 0) {
        float s = 0.0f;
#pragma unroll
        for (int w = 0; w < 8; w++) s += zw[w];
        g_Zpart[blockIdx.x * 1024 + blockIdx.y] = (double)s;
    }
}

// ---------------- l_pos ----------------
__global__ void lpos_kernel(const float* __restrict__ q,
                            const float* __restrict__ k,
                            float* __restrict__ out) {
    __shared__ float ws[8];
    const int r = threadIdx.x;
    const int v = r & 63;
    float acc = 0.0f;
#pragma unroll
    for (int c = 0; c < 4; c++) {
        int p = v + c * 64;
        if (p == r) continue;
        float s = 0.0f;
#pragma unroll 8
        for (int d = 0; d < K_DIM; d++)
            s = fmaf(q[(size_t)r * K_DIM + d], k[(size_t)p * K_DIM + d], s);
        acc += s;
    }
    float e = expf((acc * (1.0f / 3.0f)) * INV_T);
    out[(size_t)r * LDOUT] = e;
    atomicAdd(&g_rowsum[r], e);

    float t = e;
#pragma unroll
    for (int o = 16; o > 0; o >>= 1) t += __shfl_down_sync(0xffffffffu, t, o);
    if ((r & 31) == 0) ws[r >> 5] = t;
    __syncthreads();
    if (r == 0) {
        float s = 0.0f;
#pragma unroll
        for (int w = 0; w < 8; w++) s += ws[w];
        atomicAdd(&g_sumZ, (double)s);
    }
}

// ---------------- finalize: Z, invZ, probs ----------------
__global__ void finalize_kernel(const float* __restrict__ out,
                                float* __restrict__ probs_out) {
    __shared__ double zs[8];
    __shared__ float ws[8];
    const int t = threadIdx.x;       // 256 threads
    double z = 0.0;
#pragma unroll
    for (int i = 0; i < 8; i++) z += g_Zpart[t + 256 * i];
    float term = out[(size_t)t * LDOUT] / g_rowsum[t];
#pragma unroll
    for (int o = 16; o > 0; o >>= 1) {
        z    += __shfl_down_sync(0xffffffffu, z, o);
        term += __shfl_down_sync(0xffffffffu, term, o);
    }
    if ((t & 31) == 0) { zs[t >> 5] = z; ws[t >> 5] = term; }
    __syncthreads();
    if (t == 0) {
        double zz = g_sumZ;
        float ts = 0.0f;
#pragma unroll
        for (int w = 0; w < 8; w++) { zz += zs[w]; ts += ws[w]; }
        probs_out[0] = ts / (float)NBS;
        double Z = zz / ((double)NBS * (double)LDOUT) * 1.0e6;
        g_invZ = (float)(1.0 / Z);
    }
}

// ---------------- scale pass ----------------
__global__ void scale_kernel(float4* __restrict__ out) {
    const size_t n4 = (size_t)NBS * LDOUT / 4;
    size_t i = (size_t)blockIdx.x * blockDim.x + threadIdx.x;
    const float inv = g_invZ;
    if (i < n4) {
        float4 v = out[i];
        v.x *= inv; v.y *= inv; v.z *= inv; v.w *= inv;
        out[i] = v;
    }
}

// ---------------- memory-bank update ----------------
__global__ void mem_kernel(const float* __restrict__ mem,
                           const float* __restrict__ k,
                           float* __restrict__ newmem) {
    const size_t n4 = (size_t)QK * K_DIM / 4;
    size_t i4 = (size_t)blockIdx.x * blockDim.x + threadIdx.x;
    if (i4 >= n4) return;
    int row = (int)(i4 >> 5);
    float4 v;
    if (row < BATCH) {
        int d4 = (int)(i4 & 31);
        const float4* k4 = (const float4*)k;
        float4 a = k4[(size_t)row * 32 + d4];
        float4 b = k4[(size_t)(row + 64) * 32 + d4];
        float4 c = k4[(size_t)(row + 128) * 32 + d4];
        float4 d = k4[(size_t)(row + 192) * 32 + d4];
        v.x = 0.25f * (a.x + b.x + c.x + d.x);
        v.y = 0.25f * (a.y + b.y + c.y + d.y);
        v.z = 0.25f * (a.z + b.z + c.z + d.z);
        v.w = 0.25f * (a.w + b.w + c.w + d.w);
    } else {
        v = ((const float4*)mem)[i4];
    }
    float* o = newmem + i4 * 4;          // newmem base only 4B-aligned
    o[0] = v.x; o[1] = v.y; o[2] = v.z; o[3] = v.w;
}

extern "C" void kernel_launch(void* const* d_in, const int* in_sizes, int n_in,
                              void* d_out, int out_size) {
    const float* q   = (const float*)d_in[0];
    const float* k   = (const float*)d_in[1];
    const float* mem = (const float*)d_in[2];
    float* out = (float*)d_out;

    size_t mem_off = (size_t)out_size - (size_t)QK * K_DIM;
    float* newmem = out + mem_off;
    float* probs  = out + (mem_off - 1);

    cudaFuncSetAttribute(gemm_exp_kernel,
                         cudaFuncAttributeMaxDynamicSharedMemorySize, SMEM_BYTES);

    init_kernel<<<128, 256>>>(q);

    dim3 grid(2, 1024);
    gemm_exp_kernel<<<grid, 256, SMEM_BYTES>>>(mem, out);

    lpos_kernel<<<1, 256>>>(q, k, out);
    finalize_kernel<<<1, 256>>>(out, probs);

    size_t n4 = (size_t)NBS * LDOUT / 4;
    scale_kernel<<<(unsigned)((n4 + 255) / 256), 256>>>((float4*)out);

    size_t m4 = (size_t)QK * K_DIM / 4;
    mem_kernel<<<(unsigned)((m4 + 255) / 256), 256>>>(mem, k, newmem);
}

// round 5
// speedup vs baseline: 1.3312x; 1.0278x over previous
#include <cuda_runtime.h>
#include <cuda_bf16.h>
#include <cstdint>

#define K_DIM   128
#define NBS     256
#define QK      131072
#define LDOUT   (QK + 1)
#define BATCH   64
#define SSTRIDE 136                      // bf16 elems per smem row (padded)

__device__ double g_Zpart[2048];
__device__ float  g_rowsum[NBS];
__device__ float  g_invZ;
__device__ __align__(16) __nv_bfloat16 g_qhi[NBS * K_DIM];
__device__ __align__(16) __nv_bfloat16 g_qlo[NBS * K_DIM];

static __constant__ float INV_T = 1.0f / 0.07f;

__global__ void init_kernel(const float* __restrict__ q) {
    int t = blockIdx.x * blockDim.x + threadIdx.x;   // 128 x 256 = 32768
    if (t < NBS) g_rowsum[t] = 0.0f;
    float v = q[t];
    __nv_bfloat16 hi = __float2bfloat16(v);
    __nv_bfloat16 lo = __float2bfloat16(v - __bfloat162float(hi));
    g_qhi[t] = hi;
    g_qlo[t] = lo;
}

__device__ __forceinline__ uint32_t pack2(__nv_bfloat16 a, __nv_bfloat16 b) {
    return (uint32_t)__bfloat16_as_ushort(a) | ((uint32_t)__bfloat16_as_ushort(b) << 16);
}

__device__ __forceinline__ uint32_t lds_b32(const __nv_bfloat16* base, int r, int c) {
    return *reinterpret_cast<const uint32_t*>(base + r * SSTRIDE + c);
}

__device__ __forceinline__ void mma_bf16(float* c, const uint32_t* a, const uint32_t* b) {
    asm volatile(
        "mma.sync.aligned.m16n8k16.row.col.f32.bf16.bf16.f32 "
        "{%0,%1,%2,%3}, {%4,%5,%6,%7}, {%8,%9}, {%0,%1,%2,%3};"
        : "+f"(c[0]), "+f"(c[1]), "+f"(c[2]), "+f"(c[3])
        : "r"(a[0]), "r"(a[1]), "r"(a[2]), "r"(a[3]), "r"(b[0]), "r"(b[1]));
}

// grid (2, 1024): blockIdx.x = M half (128 rows), blockIdx.y = N tile (128 cols).
// 512 threads / 16 warps: wm = wid&3 (32-row band), wn = wid>>2 (32-col band).
// Warp tile 32x32: mt in {0,1} (16-row halves), nt in 0..3 (8-col slices).
#define SM_TILE (128 * SSTRIDE)
#define SMEM_BYTES (4 * SM_TILE * 2)     // A_hi A_lo B_hi B_lo

__global__ __launch_bounds__(512, 1)
void gemm_exp_kernel(const float* __restrict__ mem, float* __restrict__ out) {
    extern __shared__ __align__(16) char smem_raw[];
    __nv_bfloat16* As_hi = reinterpret_cast<__nv_bfloat16*>(smem_raw);
    __nv_bfloat16* As_lo = As_hi + SM_TILE;
    __nv_bfloat16* Bs_hi = As_lo + SM_TILE;
    __nv_bfloat16* Bs_lo = Bs_hi + SM_TILE;
    __shared__ float srows[128];
    __shared__ float zw[4];

    const int tid = threadIdx.x;
    const int wid = tid >> 5;
    const int lid = tid & 31;
    const int m0 = blockIdx.x * 128;
    const int n0 = blockIdx.y * 128;
    const int wm = wid & 3;
    const int wn = wid >> 2;

    if (tid < 128) srows[tid] = 0.0f;

    // ---- load A (precomputed hi/lo) + convert B (fp32 -> hi/lo bf16) ----
    {
        const uint4* qhi4 = reinterpret_cast<const uint4*>(g_qhi);
        const uint4* qlo4 = reinterpret_cast<const uint4*>(g_qlo);
        const float4* m4 = reinterpret_cast<const float4*>(mem);
#pragma unroll
        for (int it = 0; it < 4; it++) {
            int chunk = it * 512 + tid;      // 0..2047
            int r  = chunk >> 4;
            int c8 = chunk & 15;
            int c  = c8 * 8;
            int off = r * SSTRIDE + c;       // 16B-aligned (SSTRIDE*2 = 272 = 17*16)
            *reinterpret_cast<uint4*>(As_hi + off) = qhi4[(m0 + r) * 16 + c8];
            *reinterpret_cast<uint4*>(As_lo + off) = qlo4[(m0 + r) * 16 + c8];
            size_t bidx = ((size_t)(n0 + r) * K_DIM + c) >> 2;
            float4 f0 = m4[bidx];
            float4 f1 = m4[bidx + 1];
            float f[8] = {f0.x, f0.y, f0.z, f0.w, f1.x, f1.y, f1.z, f1.w};
            __nv_bfloat16 hi[8], lo[8];
#pragma unroll
            for (int j = 0; j < 8; j++) {
                hi[j] = __float2bfloat16(f[j]);
                lo[j] = __float2bfloat16(f[j] - __bfloat162float(hi[j]));
            }
            uint4 vh, vl;
            vh.x = pack2(hi[0], hi[1]); vh.y = pack2(hi[2], hi[3]);
            vh.z = pack2(hi[4], hi[5]); vh.w = pack2(hi[6], hi[7]);
            vl.x = pack2(lo[0], lo[1]); vl.y = pack2(lo[2], lo[3]);
            vl.z = pack2(lo[4], lo[5]); vl.w = pack2(lo[6], lo[7]);
            *reinterpret_cast<uint4*>(Bs_hi + off) = vh;
            *reinterpret_cast<uint4*>(Bs_lo + off) = vl;
        }
    }
    __syncthreads();

    // ---- mainloop: single sweep, all 3 split products per k-step ----
    float acc[2][4][4];
#pragma unroll
    for (int mt = 0; mt < 2; mt++)
#pragma unroll
        for (int nt = 0; nt < 4; nt++)
#pragma unroll
            for (int j = 0; j < 4; j++) acc[mt][nt][j] = 0.0f;

    const int ar  = lid >> 2;
    const int akc = (lid & 3) * 2;

#pragma unroll
    for (int ks = 0; ks < 8; ks++) {
        const int k0 = ks * 16;
        uint32_t ah[2][4], al[2][4], bh[4][2], bl[4][2];
#pragma unroll
        for (int mt = 0; mt < 2; mt++) {
            int rb = wm * 32 + mt * 16 + ar;
            ah[mt][0] = lds_b32(As_hi, rb,     k0 + akc);
            ah[mt][1] = lds_b32(As_hi, rb + 8, k0 + akc);
            ah[mt][2] = lds_b32(As_hi, rb,     k0 + akc + 8);
            ah[mt][3] = lds_b32(As_hi, rb + 8, k0 + akc + 8);
            al[mt][0] = lds_b32(As_lo, rb,     k0 + akc);
            al[mt][1] = lds_b32(As_lo, rb + 8, k0 + akc);
            al[mt][2] = lds_b32(As_lo, rb,     k0 + akc + 8);
            al[mt][3] = lds_b32(As_lo, rb + 8, k0 + akc + 8);
        }
#pragma unroll
        for (int nt = 0; nt < 4; nt++) {
            int nb = wn * 32 + nt * 8 + ar;
            bh[nt][0] = lds_b32(Bs_hi, nb, k0 + akc);
            bh[nt][1] = lds_b32(Bs_hi, nb, k0 + akc + 8);
            bl[nt][0] = lds_b32(Bs_lo, nb, k0 + akc);
            bl[nt][1] = lds_b32(Bs_lo, nb, k0 + akc + 8);
        }
#pragma unroll
        for (int mt = 0; mt < 2; mt++)
#pragma unroll
            for (int nt = 0; nt < 4; nt++) {
                mma_bf16(acc[mt][nt], ah[mt], bh[nt]);   // hi*hi
                mma_bf16(acc[mt][nt], al[mt], bh[nt]);   // lo*hi
                mma_bf16(acc[mt][nt], ah[mt], bl[nt]);   // hi*lo
            }
    }

    // ---- epilogue: exp, store, SMEM row sums ----
#pragma unroll
    for (int mt = 0; mt < 2; mt++) {
        const int lrow = wm * 32 + mt * 16 + ar;          // local row in tile
        const int row0 = m0 + lrow;
        float rs0 = 0.0f, rs1 = 0.0f;
#pragma unroll
        for (int nt = 0; nt < 4; nt++) {
            const size_t col = (size_t)(1 + n0 + wn * 32 + nt * 8 + (lid & 3) * 2);
            float e00 = __expf(acc[mt][nt][0] * INV_T);
            float e01 = __expf(acc[mt][nt][1] * INV_T);
            float e10 = __expf(acc[mt][nt][2] * INV_T);
            float e11 = __expf(acc[mt][nt][3] * INV_T);
            out[(size_t)row0 * LDOUT + col]           = e00;
            out[(size_t)row0 * LDOUT + col + 1]       = e01;
            out[(size_t)(row0 + 8) * LDOUT + col]     = e10;
            out[(size_t)(row0 + 8) * LDOUT + col + 1] = e11;
            rs0 += e00 + e01;
            rs1 += e10 + e11;
        }
        rs0 += __shfl_xor_sync(0xffffffffu, rs0, 1);
        rs0 += __shfl_xor_sync(0xffffffffu, rs0, 2);
        rs1 += __shfl_xor_sync(0xffffffffu, rs1, 1);
        rs1 += __shfl_xor_sync(0xffffffffu, rs1, 2);
        if ((lid & 3) == 0) {
            atomicAdd(&srows[lrow], rs0);
            atomicAdd(&srows[lrow + 8], rs1);
        }
    }
    __syncthreads();

    // one global atomic per row per CTA; block-reduce srows -> Z partial
    if (tid < 128) {
        float v = srows[tid];
        atomicAdd(&g_rowsum[m0 + tid], v);
#pragma unroll
        for (int o = 16; o > 0; o >>= 1) v += __shfl_down_sync(0xffffffffu, v, o);
        if (lid == 0) zw[tid >> 5] = v;
    }
    __syncthreads();
    if (tid == 0)
        g_Zpart[blockIdx.x * 1024 + blockIdx.y] =
            (double)(zw[0] + zw[1] + zw[2] + zw[3]);
}

// ---------------- l_pos + finalize (fused, no global atomics) ----------------
__global__ void lpos_finalize_kernel(const float* __restrict__ q,
                                     const float* __restrict__ k,
                                     float* __restrict__ out,
                                     float* __restrict__ probs_out) {
    __shared__ double zs[8];
    __shared__ float ws[8];
    const int r = threadIdx.x;       // 256 threads, 1 block
    const int v = r & 63;
    float acc = 0.0f;
#pragma unroll
    for (int c = 0; c < 4; c++) {
        int p = v + c * 64;
        if (p == r) continue;
        float s = 0.0f;
#pragma unroll 8
        for (int d = 0; d < K_DIM; d++)
            s = fmaf(q[(size_t)r * K_DIM + d], k[(size_t)p * K_DIM + d], s);
        acc += s;
    }
    float e = expf((acc * (1.0f / 3.0f)) * INV_T);
    out[(size_t)r * LDOUT] = e;

    float rowsum = g_rowsum[r] + e;          // GEMM sums complete (stream order)
    float term = e / rowsum;
    double z = (double)e;
#pragma unroll
    for (int i = 0; i < 8; i++) z += g_Zpart[r + 256 * i];
#pragma unroll
    for (int o = 16; o > 0; o >>= 1) {
        z    += __shfl_down_sync(0xffffffffu, z, o);
        term += __shfl_down_sync(0xffffffffu, term, o);
    }
    if ((r & 31) == 0) { zs[r >> 5] = z; ws[r >> 5] = term; }
    __syncthreads();
    if (r == 0) {
        double zz = 0.0;
        float ts = 0.0f;
#pragma unroll
        for (int w = 0; w < 8; w++) { zz += zs[w]; ts += ws[w]; }
        probs_out[0] = ts / (float)NBS;
        double Z = zz / ((double)NBS * (double)LDOUT) * 1.0e6;
        g_invZ = (float)(1.0 / Z);
    }
}

// ---------------- fused tail: scale out by 1/Z + memory-bank update ----------
#define NOUT4 ((size_t)NBS * LDOUT / 4)      // 8388672
#define NMEM4 ((size_t)QK * K_DIM / 4)       // 4194304

__global__ void tail_kernel(const float* __restrict__ mem,
                            const float* __restrict__ k,
                            float* __restrict__ out,
                            float* __restrict__ newmem) {
    size_t i = (size_t)blockIdx.x * blockDim.x + threadIdx.x;
    if (i < NOUT4) {
        const float inv = g_invZ;
        float4* o4 = (float4*)out;           // out base = d_out, 256B-aligned
        float4 v = o4[i];
        v.x *= inv; v.y *= inv; v.z *= inv; v.w *= inv;
        o4[i] = v;
    } else {
        size_t j = i - NOUT4;
        if (j >= NMEM4) return;
        int row = (int)(j >> 5);
        float4 v;
        if (row < BATCH) {
            int d4 = (int)(j & 31);
            const float4* k4 = (const float4*)k;
            float4 a = k4[(size_t)row * 32 + d4];
            float4 b = k4[(size_t)(row + 64) * 32 + d4];
            float4 c = k4[(size_t)(row + 128) * 32 + d4];
            float4 d = k4[(size_t)(row + 192) * 32 + d4];
            v.x = 0.25f * (a.x + b.x + c.x + d.x);
            v.y = 0.25f * (a.y + b.y + c.y + d.y);
            v.z = 0.25f * (a.z + b.z + c.z + d.z);
            v.w = 0.25f * (a.w + b.w + c.w + d.w);
        } else {
            v = ((const float4*)mem)[j];
        }
        float* o = newmem + j * 4;           // newmem base only 4B-aligned
        o[0] = v.x; o[1] = v.y; o[2] = v.z; o[3] = v.w;
    }
}

extern "C" void kernel_launch(void* const* d_in, const int* in_sizes, int n_in,
                              void* d_out, int out_size) {
    const float* q   = (const float*)d_in[0];
    const float* k   = (const float*)d_in[1];
    const float* mem = (const float*)d_in[2];
    float* out = (float*)d_out;

    size_t mem_off = (size_t)out_size - (size_t)QK * K_DIM;
    float* newmem = out + mem_off;
    float* probs  = out + (mem_off - 1);

    cudaFuncSetAttribute(gemm_exp_kernel,
                         cudaFuncAttributeMaxDynamicSharedMemorySize, SMEM_BYTES);

    init_kernel<<<128, 256>>>(q);

    dim3 grid(2, 1024);
    gemm_exp_kernel<<<grid, 512, SMEM_BYTES>>>(mem, out);

    lpos_finalize_kernel<<<1, 256>>>(q, k, out, probs);

    size_t total = NOUT4 + NMEM4;
    tail_kernel<<<(unsigned)((total + 255) / 256), 256>>>(mem, k, out, newmem);
}

// round 6
// speedup vs baseline: 1.3493x; 1.0136x over previous
#include <cuda_runtime.h>
#include <cuda_bf16.h>
#include <cstdint>

#define K_DIM   128
#define NBS     256
#define QK      131072
#define LDOUT   (QK + 1)
#define BATCH   64
#define SSTRIDE 136                      // bf16 elems per smem operand row
#define STG_S   136                      // floats per stage row (8 mod 32 -> conflict-free STS.64)

#define NGEMM   2048                     // 2 x 1024 gemm CTAs
#define NCOPY   512                      // co-scheduled mem-copy CTAs
#define NOUT4   ((size_t)NBS * LDOUT / 4)
#define NMEM4   ((size_t)QK * K_DIM / 4)

__device__ double g_Zpart[NGEMM];
__device__ float  g_rowsum[NBS];
__device__ float  g_invZ;
__device__ __align__(16) __nv_bfloat16 g_qhi[NBS * K_DIM];
__device__ __align__(16) __nv_bfloat16 g_qlo[NBS * K_DIM];

static __constant__ float INV_T = 1.0f / 0.07f;

__global__ void init_kernel(const float* __restrict__ q) {
    int t = blockIdx.x * blockDim.x + threadIdx.x;   // 128 x 256 = 32768
    if (t < NBS) g_rowsum[t] = 0.0f;
    float v = q[t];
    __nv_bfloat16 hi = __float2bfloat16(v);
    __nv_bfloat16 lo = __float2bfloat16(v - __bfloat162float(hi));
    g_qhi[t] = hi;
    g_qlo[t] = lo;
}

__device__ __forceinline__ uint32_t pack2(__nv_bfloat16 a, __nv_bfloat16 b) {
    return (uint32_t)__bfloat16_as_ushort(a) | ((uint32_t)__bfloat16_as_ushort(b) << 16);
}

__device__ __forceinline__ uint32_t lds_b32(const __nv_bfloat16* base, int r, int c) {
    return *reinterpret_cast<const uint32_t*>(base + r * SSTRIDE + c);
}

__device__ __forceinline__ void mma_bf16(float* c, const uint32_t* a, const uint32_t* b) {
    asm volatile(
        "mma.sync.aligned.m16n8k16.row.col.f32.bf16.bf16.f32 "
        "{%0,%1,%2,%3}, {%4,%5,%6,%7}, {%8,%9}, {%0,%1,%2,%3};"
        : "+f"(c[0]), "+f"(c[1]), "+f"(c[2]), "+f"(c[3])
        : "r"(a[0]), "r"(a[1]), "r"(a[2]), "r"(a[3]), "r"(b[0]), "r"(b[1]));
}

// 1D grid of NGEMM + NCOPY blocks, 512 threads.
//   id < NGEMM: gemm block; bx = id&1 (M half), by = id>>1 (N tile).
//               Adjacent ids share the same B tile -> L2 reuse.
//   id >= NGEMM: pure streaming copy of the memory bank (overlaps gemm compute).
#define SM_TILE (128 * SSTRIDE)
#define SMEM_BYTES (4 * SM_TILE * 2)     // A_hi A_lo B_hi B_lo (stage reuses this)

__global__ __launch_bounds__(512, 1)
void gemm_exp_kernel(const float* __restrict__ mem,
                     const float* __restrict__ kin,
                     float* __restrict__ out,
                     float* __restrict__ newmem) {
    const int tid = threadIdx.x;
    const int bid = blockIdx.x;

    // ---------- co-scheduled memory-bank copy blocks ----------
    if (bid >= NGEMM) {
        const int cid = bid - NGEMM;                 // 0..511
        const float4* m4 = (const float4*)mem;
        const float4* k4 = (const float4*)kin;
#pragma unroll
        for (int it = 0; it < 16; it++) {
            size_t j = (size_t)cid * (NMEM4 / NCOPY) + (size_t)it * 512 + tid;
            int row = (int)(j >> 5);
            float4 v;
            if (row < BATCH) {
                int d4 = (int)(j & 31);
                float4 a = k4[(size_t)row * 32 + d4];
                float4 b = k4[(size_t)(row + 64) * 32 + d4];
                float4 c = k4[(size_t)(row + 128) * 32 + d4];
                float4 d = k4[(size_t)(row + 192) * 32 + d4];
                v.x = 0.25f * (a.x + b.x + c.x + d.x);
                v.y = 0.25f * (a.y + b.y + c.y + d.y);
                v.z = 0.25f * (a.z + b.z + c.z + d.z);
                v.w = 0.25f * (a.w + b.w + c.w + d.w);
            } else {
                v = m4[j];
            }
            float* o = newmem + j * 4;               // base only 4B-aligned
            o[0] = v.x; o[1] = v.y; o[2] = v.z; o[3] = v.w;
        }
        return;
    }

    // ---------- gemm blocks ----------
    extern __shared__ __align__(16) char smem_raw[];
    __nv_bfloat16* As_hi = reinterpret_cast<__nv_bfloat16*>(smem_raw);
    __nv_bfloat16* As_lo = As_hi + SM_TILE;
    __nv_bfloat16* Bs_hi = As_lo + SM_TILE;
    __nv_bfloat16* Bs_lo = Bs_hi + SM_TILE;
    float* stage = reinterpret_cast<float*>(smem_raw);   // reused after mainloop
    __shared__ float srows[128];
    __shared__ float zw[4];

    const int wid = tid >> 5;
    const int lid = tid & 31;
    const int m0 = (bid & 1) * 128;
    const int n0 = (bid >> 1) * 128;
    const int wm = wid & 3;
    const int wn = wid >> 2;

    // ---- load A (precomputed hi/lo) + convert B (fp32 -> hi/lo bf16) ----
    {
        const uint4* qhi4 = reinterpret_cast<const uint4*>(g_qhi);
        const uint4* qlo4 = reinterpret_cast<const uint4*>(g_qlo);
        const float4* m4 = reinterpret_cast<const float4*>(mem);
#pragma unroll
        for (int it = 0; it < 4; it++) {
            int chunk = it * 512 + tid;      // 0..2047
            int r  = chunk >> 4;
            int c8 = chunk & 15;
            int c  = c8 * 8;
            int off = r * SSTRIDE + c;       // 16B-aligned
            *reinterpret_cast<uint4*>(As_hi + off) = qhi4[(m0 + r) * 16 + c8];
            *reinterpret_cast<uint4*>(As_lo + off) = qlo4[(m0 + r) * 16 + c8];
            size_t bidx = ((size_t)(n0 + r) * K_DIM + c) >> 2;
            float4 f0 = m4[bidx];
            float4 f1 = m4[bidx + 1];
            float f[8] = {f0.x, f0.y, f0.z, f0.w, f1.x, f1.y, f1.z, f1.w};
            __nv_bfloat16 hi[8], lo[8];
#pragma unroll
            for (int j = 0; j < 8; j++) {
                hi[j] = __float2bfloat16(f[j]);
                lo[j] = __float2bfloat16(f[j] - __bfloat162float(hi[j]));
            }
            uint4 vh, vl;
            vh.x = pack2(hi[0], hi[1]); vh.y = pack2(hi[2], hi[3]);
            vh.z = pack2(hi[4], hi[5]); vh.w = pack2(hi[6], hi[7]);
            vl.x = pack2(lo[0], lo[1]); vl.y = pack2(lo[2], lo[3]);
            vl.z = pack2(lo[4], lo[5]); vl.w = pack2(lo[6], lo[7]);
            *reinterpret_cast<uint4*>(Bs_hi + off) = vh;
            *reinterpret_cast<uint4*>(Bs_lo + off) = vl;
        }
    }
    __syncthreads();

    // ---- mainloop: all 3 split products per k-step ----
    float acc[2][4][4];
#pragma unroll
    for (int mt = 0; mt < 2; mt++)
#pragma unroll
        for (int nt = 0; nt < 4; nt++)
#pragma unroll
            for (int j = 0; j < 4; j++) acc[mt][nt][j] = 0.0f;

    const int ar  = lid >> 2;
    const int akc = (lid & 3) * 2;

#pragma unroll
    for (int ks = 0; ks < 8; ks++) {
        const int k0 = ks * 16;
        uint32_t ah[2][4], al[2][4], bh[4][2], bl[4][2];
#pragma unroll
        for (int mt = 0; mt < 2; mt++) {
            int rb = wm * 32 + mt * 16 + ar;
            ah[mt][0] = lds_b32(As_hi, rb,     k0 + akc);
            ah[mt][1] = lds_b32(As_hi, rb + 8, k0 + akc);
            ah[mt][2] = lds_b32(As_hi, rb,     k0 + akc + 8);
            ah[mt][3] = lds_b32(As_hi, rb + 8, k0 + akc + 8);
            al[mt][0] = lds_b32(As_lo, rb,     k0 + akc);
            al[mt][1] = lds_b32(As_lo, rb + 8, k0 + akc);
            al[mt][2] = lds_b32(As_lo, rb,     k0 + akc + 8);
            al[mt][3] = lds_b32(As_lo, rb + 8, k0 + akc + 8);
        }
#pragma unroll
        for (int nt = 0; nt < 4; nt++) {
            int nb = wn * 32 + nt * 8 + ar;
            bh[nt][0] = lds_b32(Bs_hi, nb, k0 + akc);
            bh[nt][1] = lds_b32(Bs_hi, nb, k0 + akc + 8);
            bl[nt][0] = lds_b32(Bs_lo, nb, k0 + akc);
            bl[nt][1] = lds_b32(Bs_lo, nb, k0 + akc + 8);
        }
#pragma unroll
        for (int mt = 0; mt < 2; mt++)
#pragma unroll
            for (int nt = 0; nt < 4; nt++) {
                mma_bf16(acc[mt][nt], ah[mt], bh[nt]);   // hi*hi
                mma_bf16(acc[mt][nt], al[mt], bh[nt]);   // lo*hi
                mma_bf16(acc[mt][nt], ah[mt], bl[nt]);   // hi*lo
            }
    }
    __syncthreads();     // operand smem dead; reuse as stage

    // ---- epilogue phase 1: exp -> SMEM stage (STS.64, conflict-free) ----
#pragma unroll
    for (int mt = 0; mt < 2; mt++) {
        const int lrow = wm * 32 + mt * 16 + ar;
        const int colw = wn * 32 + (lid & 3) * 2;
#pragma unroll
        for (int nt = 0; nt < 4; nt++) {
            float e00 = __expf(acc[mt][nt][0] * INV_T);
            float e01 = __expf(acc[mt][nt][1] * INV_T);
            float e10 = __expf(acc[mt][nt][2] * INV_T);
            float e11 = __expf(acc[mt][nt][3] * INV_T);
            float2* s0 = reinterpret_cast<float2*>(stage + lrow * STG_S + colw + nt * 8);
            float2* s1 = reinterpret_cast<float2*>(stage + (lrow + 8) * STG_S + colw + nt * 8);
            *s0 = make_float2(e00, e01);
            *s1 = make_float2(e10, e11);
        }
    }
    __syncthreads();

    // ---- epilogue phase 2: coalesced stores + row sums ----
    {
        const size_t obase = (size_t)m0 * LDOUT + 1 + n0;
#pragma unroll
        for (int rr = 0; rr < 8; rr++) {
            int row = wid * 8 + rr;
            float rsum = 0.0f;
#pragma unroll
            for (int j = 0; j < 4; j++) {
                float x = stage[row * STG_S + j * 32 + lid];
                out[obase + (size_t)row * LDOUT + j * 32 + lid] = x;
                rsum += x;
            }
#pragma unroll
            for (int o = 16; o > 0; o >>= 1)
                rsum += __shfl_down_sync(0xffffffffu, rsum, o);
            if (lid == 0) srows[row] = rsum;     // single writer
        }
    }
    __syncthreads();

    if (tid < 128) {
        float v = srows[tid];
        atomicAdd(&g_rowsum[m0 + tid], v);
#pragma unroll
        for (int o = 16; o > 0; o >>= 1) v += __shfl_down_sync(0xffffffffu, v, o);
        if (lid == 0) zw[tid >> 5] = v;
    }
    __syncthreads();
    if (tid == 0)
        g_Zpart[bid] = (double)(zw[0] + zw[1] + zw[2] + zw[3]);
}

// ---------------- l_pos + finalize (fused, single block) ----------------
__global__ void lpos_finalize_kernel(const float* __restrict__ q,
                                     const float* __restrict__ k,
                                     float* __restrict__ out,
                                     float* __restrict__ probs_out) {
    __shared__ double zs[8];
    __shared__ float ws[8];
    const int r = threadIdx.x;       // 256 threads
    const int v = r & 63;
    float acc = 0.0f;
#pragma unroll
    for (int c = 0; c < 4; c++) {
        int p = v + c * 64;
        if (p == r) continue;
        float s = 0.0f;
#pragma unroll 8
        for (int d = 0; d < K_DIM; d++)
            s = fmaf(q[(size_t)r * K_DIM + d], k[(size_t)p * K_DIM + d], s);
        acc += s;
    }
    float e = expf((acc * (1.0f / 3.0f)) * INV_T);
    out[(size_t)r * LDOUT] = e;

    float rowsum = g_rowsum[r] + e;
    float term = e / rowsum;
    double z = (double)e;
#pragma unroll
    for (int i = 0; i < 8; i++) z += g_Zpart[r + 256 * i];
#pragma unroll
    for (int o = 16; o > 0; o >>= 1) {
        z    += __shfl_down_sync(0xffffffffu, z, o);
        term += __shfl_down_sync(0xffffffffu, term, o);
    }
    if ((r & 31) == 0) { zs[r >> 5] = z; ws[r >> 5] = term; }
    __syncthreads();
    if (r == 0) {
        double zz = 0.0;
        float ts = 0.0f;
#pragma unroll
        for (int w = 0; w < 8; w++) { zz += zs[w]; ts += ws[w]; }
        probs_out[0] = ts / (float)NBS;
        double Z = zz / ((double)NBS * (double)LDOUT) * 1.0e6;
        g_invZ = (float)(1.0 / Z);
    }
}

// ---------------- tail: scale out by 1/Z ----------------
__global__ void scale_kernel(float4* __restrict__ out) {
    size_t i = (size_t)blockIdx.x * blockDim.x + threadIdx.x;
    const float inv = g_invZ;
    if (i < NOUT4) {
        float4 v = out[i];
        v.x *= inv; v.y *= inv; v.z *= inv; v.w *= inv;
        out[i] = v;
    }
}

extern "C" void kernel_launch(void* const* d_in, const int* in_sizes, int n_in,
                              void* d_out, int out_size) {
    const float* q   = (const float*)d_in[0];
    const float* k   = (const float*)d_in[1];
    const float* mem = (const float*)d_in[2];
    float* out = (float*)d_out;

    size_t mem_off = (size_t)out_size - (size_t)QK * K_DIM;
    float* newmem = out + mem_off;
    float* probs  = out + (mem_off - 1);

    cudaFuncSetAttribute(gemm_exp_kernel,
                         cudaFuncAttributeMaxDynamicSharedMemorySize, SMEM_BYTES);

    init_kernel<<<128, 256>>>(q);

    gemm_exp_kernel<<<NGEMM + NCOPY, 512, SMEM_BYTES>>>(mem, k, out, newmem);

    lpos_finalize_kernel<<<1, 256>>>(q, k, out, probs);

    scale_kernel<<<(unsigned)((NOUT4 + 255) / 256), 256>>>((float4*)out);
}

// round 7
// speedup vs baseline: 1.3574x; 1.0060x over previous
#include <cuda_runtime.h>
#include <cuda_bf16.h>
#include <cstdint>

#define K_DIM   128
#define NBS     256
#define QK      131072
#define LDOUT   (QK + 1)
#define BATCH   64
#define SSTRIDE 136                      // bf16 elems per smem operand row
#define STG_S   136                      // floats per stage row (8 mod 32 -> conflict-free STS.64)

#define NGEMM   2048                     // 2 x 1024 gemm CTAs
#define NCOPY   512                      // co-scheduled mem-copy CTAs
#define NOUT4   ((size_t)NBS * LDOUT / 4)
#define NMEM4   ((size_t)QK * K_DIM / 4)

__device__ double g_Zpart[NGEMM];
__device__ float  g_rowsum[NBS];
__device__ float  g_invZ;
__device__ __align__(16) __nv_bfloat16 g_qhi[NBS * K_DIM];
__device__ __align__(16) __nv_bfloat16 g_qlo[NBS * K_DIM];

static __constant__ float INV_T = 1.0f / 0.07f;

__global__ void init_kernel(const float* __restrict__ q) {
    int t = blockIdx.x * blockDim.x + threadIdx.x;   // 128 x 256 = 32768
    if (t < NBS) g_rowsum[t] = 0.0f;
    float v = q[t];
    __nv_bfloat16 hi = __float2bfloat16(v);
    __nv_bfloat16 lo = __float2bfloat16(v - __bfloat162float(hi));
    g_qhi[t] = hi;
    g_qlo[t] = lo;
}

__device__ __forceinline__ uint32_t pack2(__nv_bfloat16 a, __nv_bfloat16 b) {
    return (uint32_t)__bfloat16_as_ushort(a) | ((uint32_t)__bfloat16_as_ushort(b) << 16);
}

__device__ __forceinline__ uint32_t lds_b32(const __nv_bfloat16* base, int r, int c) {
    return *reinterpret_cast<const uint32_t*>(base + r * SSTRIDE + c);
}

__device__ __forceinline__ void mma_bf16(float* c, const uint32_t* a, const uint32_t* b) {
    asm volatile(
        "mma.sync.aligned.m16n8k16.row.col.f32.bf16.bf16.f32 "
        "{%0,%1,%2,%3}, {%4,%5,%6,%7}, {%8,%9}, {%0,%1,%2,%3};"
        : "+f"(c[0]), "+f"(c[1]), "+f"(c[2]), "+f"(c[3])
        : "r"(a[0]), "r"(a[1]), "r"(a[2]), "r"(a[3]), "r"(b[0]), "r"(b[1]));
}

// 1D grid of NGEMM + NCOPY blocks, 512 threads.
//   id < NGEMM: gemm block; bx = id&1 (M half), by = id>>1 (N tile).
//               Adjacent ids share the same B tile -> L2 reuse.
//   id >= NGEMM: pure streaming copy of the memory bank (overlaps gemm compute).
#define SM_TILE (128 * SSTRIDE)
#define SMEM_BYTES (4 * SM_TILE * 2)     // A_hi A_lo B_hi B_lo (stage reuses this)

__global__ __launch_bounds__(512, 1)
void gemm_exp_kernel(const float* __restrict__ mem,
                     const float* __restrict__ kin,
                     float* __restrict__ out,
                     float* __restrict__ newmem) {
    const int tid = threadIdx.x;
    const int bid = blockIdx.x;

    // ---------- co-scheduled memory-bank copy blocks ----------
    if (bid >= NGEMM) {
        const int cid = bid - NGEMM;                 // 0..511
        const float4* m4 = (const float4*)mem;
        const float4* k4 = (const float4*)kin;
#pragma unroll
        for (int it = 0; it < 16; it++) {
            size_t j = (size_t)cid * (NMEM4 / NCOPY) + (size_t)it * 512 + tid;
            int row = (int)(j >> 5);
            float4 v;
            if (row < BATCH) {
                int d4 = (int)(j & 31);
                float4 a = k4[(size_t)row * 32 + d4];
                float4 b = k4[(size_t)(row + 64) * 32 + d4];
                float4 c = k4[(size_t)(row + 128) * 32 + d4];
                float4 d = k4[(size_t)(row + 192) * 32 + d4];
                v.x = 0.25f * (a.x + b.x + c.x + d.x);
                v.y = 0.25f * (a.y + b.y + c.y + d.y);
                v.z = 0.25f * (a.z + b.z + c.z + d.z);
                v.w = 0.25f * (a.w + b.w + c.w + d.w);
            } else {
                v = m4[j];
            }
            float* o = newmem + j * 4;               // base only 4B-aligned
            o[0] = v.x; o[1] = v.y; o[2] = v.z; o[3] = v.w;
        }
        return;
    }

    // ---------- gemm blocks ----------
    extern __shared__ __align__(16) char smem_raw[];
    __nv_bfloat16* As_hi = reinterpret_cast<__nv_bfloat16*>(smem_raw);
    __nv_bfloat16* As_lo = As_hi + SM_TILE;
    __nv_bfloat16* Bs_hi = As_lo + SM_TILE;
    __nv_bfloat16* Bs_lo = Bs_hi + SM_TILE;
    float* stage = reinterpret_cast<float*>(smem_raw);   // reused after mainloop
    __shared__ float srows[128];
    __shared__ float zw[4];

    const int wid = tid >> 5;
    const int lid = tid & 31;
    const int m0 = (bid & 1) * 128;
    const int n0 = (bid >> 1) * 128;
    const int wm = wid & 3;
    const int wn = wid >> 2;

    // ---- load A (precomputed hi/lo) + convert B (fp32 -> hi/lo bf16) ----
    {
        const uint4* qhi4 = reinterpret_cast<const uint4*>(g_qhi);
        const uint4* qlo4 = reinterpret_cast<const uint4*>(g_qlo);
        const float4* m4 = reinterpret_cast<const float4*>(mem);
#pragma unroll
        for (int it = 0; it < 4; it++) {
            int chunk = it * 512 + tid;      // 0..2047
            int r  = chunk >> 4;
            int c8 = chunk & 15;
            int c  = c8 * 8;
            int off = r * SSTRIDE + c;       // 16B-aligned
            *reinterpret_cast<uint4*>(As_hi + off) = qhi4[(m0 + r) * 16 + c8];
            *reinterpret_cast<uint4*>(As_lo + off) = qlo4[(m0 + r) * 16 + c8];
            size_t bidx = ((size_t)(n0 + r) * K_DIM + c) >> 2;
            float4 f0 = m4[bidx];
            float4 f1 = m4[bidx + 1];
            float f[8] = {f0.x, f0.y, f0.z, f0.w, f1.x, f1.y, f1.z, f1.w};
            __nv_bfloat16 hi[8], lo[8];
#pragma unroll
            for (int j = 0; j < 8; j++) {
                hi[j] = __float2bfloat16(f[j]);
                lo[j] = __float2bfloat16(f[j] - __bfloat162float(hi[j]));
            }
            uint4 vh, vl;
            vh.x = pack2(hi[0], hi[1]); vh.y = pack2(hi[2], hi[3]);
            vh.z = pack2(hi[4], hi[5]); vh.w = pack2(hi[6], hi[7]);
            vl.x = pack2(lo[0], lo[1]); vl.y = pack2(lo[2], lo[3]);
            vl.z = pack2(lo[4], lo[5]); vl.w = pack2(lo[6], lo[7]);
            *reinterpret_cast<uint4*>(Bs_hi + off) = vh;
            *reinterpret_cast<uint4*>(Bs_lo + off) = vl;
        }
    }
    __syncthreads();

    // ---- mainloop: all 3 split products per k-step ----
    float acc[2][4][4];
#pragma unroll
    for (int mt = 0; mt < 2; mt++)
#pragma unroll
        for (int nt = 0; nt < 4; nt++)
#pragma unroll
            for (int j = 0; j < 4; j++) acc[mt][nt][j] = 0.0f;

    const int ar  = lid >> 2;
    const int akc = (lid & 3) * 2;

#pragma unroll
    for (int ks = 0; ks < 8; ks++) {
        const int k0 = ks * 16;
        uint32_t ah[2][4], al[2][4], bh[4][2], bl[4][2];
#pragma unroll
        for (int mt = 0; mt < 2; mt++) {
            int rb = wm * 32 + mt * 16 + ar;
            ah[mt][0] = lds_b32(As_hi, rb,     k0 + akc);
            ah[mt][1] = lds_b32(As_hi, rb + 8, k0 + akc);
            ah[mt][2] = lds_b32(As_hi, rb,     k0 + akc + 8);
            ah[mt][3] = lds_b32(As_hi, rb + 8, k0 + akc + 8);
            al[mt][0] = lds_b32(As_lo, rb,     k0 + akc);
            al[mt][1] = lds_b32(As_lo, rb + 8, k0 + akc);
            al[mt][2] = lds_b32(As_lo, rb,     k0 + akc + 8);
            al[mt][3] = lds_b32(As_lo, rb + 8, k0 + akc + 8);
        }
#pragma unroll
        for (int nt = 0; nt < 4; nt++) {
            int nb = wn * 32 + nt * 8 + ar;
            bh[nt][0] = lds_b32(Bs_hi, nb, k0 + akc);
            bh[nt][1] = lds_b32(Bs_hi, nb, k0 + akc + 8);
            bl[nt][0] = lds_b32(Bs_lo, nb, k0 + akc);
            bl[nt][1] = lds_b32(Bs_lo, nb, k0 + akc + 8);
        }
#pragma unroll
        for (int mt = 0; mt < 2; mt++)
#pragma unroll
            for (int nt = 0; nt < 4; nt++) {
                mma_bf16(acc[mt][nt], ah[mt], bh[nt]);   // hi*hi
                mma_bf16(acc[mt][nt], al[mt], bh[nt]);   // lo*hi
                mma_bf16(acc[mt][nt], ah[mt], bl[nt]);   // hi*lo
            }
    }
    __syncthreads();     // operand smem dead; reuse as stage

    // ---- epilogue phase 1: exp -> SMEM stage (STS.64, conflict-free) ----
#pragma unroll
    for (int mt = 0; mt < 2; mt++) {
        const int lrow = wm * 32 + mt * 16 + ar;
        const int colw = wn * 32 + (lid & 3) * 2;
#pragma unroll
        for (int nt = 0; nt < 4; nt++) {
            float e00 = __expf(acc[mt][nt][0] * INV_T);
            float e01 = __expf(acc[mt][nt][1] * INV_T);
            float e10 = __expf(acc[mt][nt][2] * INV_T);
            float e11 = __expf(acc[mt][nt][3] * INV_T);
            float2* s0 = reinterpret_cast<float2*>(stage + lrow * STG_S + colw + nt * 8);
            float2* s1 = reinterpret_cast<float2*>(stage + (lrow + 8) * STG_S + colw + nt * 8);
            *s0 = make_float2(e00, e01);
            *s1 = make_float2(e10, e11);
        }
    }
    __syncthreads();

    // ---- epilogue phase 2: coalesced stores + row sums ----
    {
        const size_t obase = (size_t)m0 * LDOUT + 1 + n0;
#pragma unroll
        for (int rr = 0; rr < 8; rr++) {
            int row = wid * 8 + rr;
            float rsum = 0.0f;
#pragma unroll
            for (int j = 0; j < 4; j++) {
                float x = stage[row * STG_S + j * 32 + lid];
                out[obase + (size_t)row * LDOUT + j * 32 + lid] = x;
                rsum += x;
            }
#pragma unroll
            for (int o = 16; o > 0; o >>= 1)
                rsum += __shfl_down_sync(0xffffffffu, rsum, o);
            if (lid == 0) srows[row] = rsum;     // single writer
        }
    }
    __syncthreads();

    if (tid < 128) {
        float v = srows[tid];
        atomicAdd(&g_rowsum[m0 + tid], v);
#pragma unroll
        for (int o = 16; o > 0; o >>= 1) v += __shfl_down_sync(0xffffffffu, v, o);
        if (lid == 0) zw[tid >> 5] = v;
    }
    __syncthreads();
    if (tid == 0)
        g_Zpart[bid] = (double)(zw[0] + zw[1] + zw[2] + zw[3]);
}

// ---------------- l_pos + finalize (fused, single block) ----------------
__global__ void lpos_finalize_kernel(const float* __restrict__ q,
                                     const float* __restrict__ k,
                                     float* __restrict__ out,
                                     float* __restrict__ probs_out) {
    __shared__ double zs[8];
    __shared__ float ws[8];
    const int r = threadIdx.x;       // 256 threads
    const int v = r & 63;
    float acc = 0.0f;
#pragma unroll
    for (int c = 0; c < 4; c++) {
        int p = v + c * 64;
        if (p == r) continue;
        float s = 0.0f;
#pragma unroll 8
        for (int d = 0; d < K_DIM; d++)
            s = fmaf(q[(size_t)r * K_DIM + d], k[(size_t)p * K_DIM + d], s);
        acc += s;
    }
    float e = expf((acc * (1.0f / 3.0f)) * INV_T);
    out[(size_t)r * LDOUT] = e;

    float rowsum = g_rowsum[r] + e;
    float term = e / rowsum;
    double z = (double)e;
#pragma unroll
    for (int i = 0; i < 8; i++) z += g_Zpart[r + 256 * i];
#pragma unroll
    for (int o = 16; o > 0; o >>= 1) {
        z    += __shfl_down_sync(0xffffffffu, z, o);
        term += __shfl_down_sync(0xffffffffu, term, o);
    }
    if ((r & 31) == 0) { zs[r >> 5] = z; ws[r >> 5] = term; }
    __syncthreads();
    if (r == 0) {
        double zz = 0.0;
        float ts = 0.0f;
#pragma unroll
        for (int w = 0; w < 8; w++) { zz += zs[w]; ts += ws[w]; }
        probs_out[0] = ts / (float)NBS;
        double Z = zz / ((double)NBS * (double)LDOUT) * 1.0e6;
        g_invZ = (float)(1.0 / Z);
    }
}

// ---------------- tail: scale out by 1/Z ----------------
__global__ void scale_kernel(float4* __restrict__ out) {
    size_t i = (size_t)blockIdx.x * blockDim.x + threadIdx.x;
    const float inv = g_invZ;
    if (i < NOUT4) {
        float4 v = out[i];
        v.x *= inv; v.y *= inv; v.z *= inv; v.w *= inv;
        out[i] = v;
    }
}

extern "C" void kernel_launch(void* const* d_in, const int* in_sizes, int n_in,
                              void* d_out, int out_size) {
    const float* q   = (const float*)d_in[0];
    const float* k   = (const float*)d_in[1];
    const float* mem = (const float*)d_in[2];
    float* out = (float*)d_out;

    size_t mem_off = (size_t)out_size - (size_t)QK * K_DIM;
    float* newmem = out + mem_off;
    float* probs  = out + (mem_off - 1);

    cudaFuncSetAttribute(gemm_exp_kernel,
                         cudaFuncAttributeMaxDynamicSharedMemorySize, SMEM_BYTES);

    init_kernel<<<128, 256>>>(q);

    gemm_exp_kernel<<<NGEMM + NCOPY, 512, SMEM_BYTES>>>(mem, k, out, newmem);

    lpos_finalize_kernel<<<1, 256>>>(q, k, out, probs);

    scale_kernel<<<(unsigned)((NOUT4 + 255) / 256), 256>>>((float4*)out);
}

// round 8
// speedup vs baseline: 1.5390x; 1.1338x over previous
#include <cuda_runtime.h>
#include <cuda_fp16.h>
#include <cstdint>

#define K_DIM   128
#define NBS     256
#define QK      131072
#define LDOUT   (QK + 1)
#define BATCH   64
#define SSTRIDE 136                      // fp16 elems per smem operand row
#define STG_S   136                      // floats per stage row

#define NGEMM   2048                     // 2 x 1024 gemm CTAs
#define NCOPY   512                      // co-scheduled mem-copy CTAs
#define NOUT4   ((size_t)NBS * LDOUT / 4)
#define NMEM4   ((size_t)QK * K_DIM / 4)

__device__ double g_Zpart[NGEMM];
__device__ float  g_rowsum[NBS];
__device__ float  g_invZ;
__device__ __align__(16) __half g_qh[NBS * K_DIM];

static __constant__ float INV_T = 1.0f / 0.07f;

__global__ void init_kernel(const float* __restrict__ q) {
    int t = blockIdx.x * blockDim.x + threadIdx.x;   // 128 x 256 = 32768
    if (t < NBS) g_rowsum[t] = 0.0f;
    g_qh[t] = __float2half_rn(q[t]);
}

__device__ __forceinline__ uint32_t pack2h(__half a, __half b) {
    return (uint32_t)__half_as_ushort(a) | ((uint32_t)__half_as_ushort(b) << 16);
}

__device__ __forceinline__ uint32_t lds_b32(const __half* base, int r, int c) {
    return *reinterpret_cast<const uint32_t*>(base + r * SSTRIDE + c);
}

__device__ __forceinline__ void mma_f16(float* c, const uint32_t* a, const uint32_t* b) {
    asm volatile(
        "mma.sync.aligned.m16n8k16.row.col.f32.f16.f16.f32 "
        "{%0,%1,%2,%3}, {%4,%5,%6,%7}, {%8,%9}, {%0,%1,%2,%3};"
        : "+f"(c[0]), "+f"(c[1]), "+f"(c[2]), "+f"(c[3])
        : "r"(a[0]), "r"(a[1]), "r"(a[2]), "r"(a[3]), "r"(b[0]), "r"(b[1]));
}

// 1D grid of NGEMM + NCOPY blocks, 512 threads.
//   id < NGEMM: gemm block; bx = id&1 (M half), by = id>>1 (N tile).
//   id >= NGEMM: streaming copy of the memory bank (overlaps gemm compute).
#define SM_TILE (128 * SSTRIDE)
#define SMEM_BYTES (128 * STG_S * 4)     // stage (69632 B) >= 2 fp16 operand tiles

__global__ __launch_bounds__(512, 1)
void gemm_exp_kernel(const float* __restrict__ mem,
                     const float* __restrict__ kin,
                     float* __restrict__ out,
                     float* __restrict__ newmem) {
    const int tid = threadIdx.x;
    const int bid = blockIdx.x;

    // ---------- co-scheduled memory-bank copy blocks ----------
    if (bid >= NGEMM) {
        const int cid = bid - NGEMM;                 // 0..511
        const float4* m4 = (const float4*)mem;
        const float4* k4 = (const float4*)kin;
#pragma unroll
        for (int it = 0; it < 16; it++) {
            size_t j = (size_t)cid * (NMEM4 / NCOPY) + (size_t)it * 512 + tid;
            int row = (int)(j >> 5);
            float4 v;
            if (row < BATCH) {
                int d4 = (int)(j & 31);
                float4 a = k4[(size_t)row * 32 + d4];
                float4 b = k4[(size_t)(row + 64) * 32 + d4];
                float4 c = k4[(size_t)(row + 128) * 32 + d4];
                float4 d = k4[(size_t)(row + 192) * 32 + d4];
                v.x = 0.25f * (a.x + b.x + c.x + d.x);
                v.y = 0.25f * (a.y + b.y + c.y + d.y);
                v.z = 0.25f * (a.z + b.z + c.z + d.z);
                v.w = 0.25f * (a.w + b.w + c.w + d.w);
            } else {
                v = m4[j];
            }
            float* o = newmem + j * 4;               // base only 4B-aligned
            o[0] = v.x; o[1] = v.y; o[2] = v.z; o[3] = v.w;
        }
        return;
    }

    // ---------- gemm blocks ----------
    extern __shared__ __align__(16) char smem_raw[];
    __half* As = reinterpret_cast<__half*>(smem_raw);
    __half* Bs = As + SM_TILE;
    float* stage = reinterpret_cast<float*>(smem_raw);   // reused after mainloop
    __shared__ float srows[128];
    __shared__ float zw[4];

    const int wid = tid >> 5;
    const int lid = tid & 31;
    const int m0 = (bid & 1) * 128;
    const int n0 = (bid >> 1) * 128;
    const int wm = wid & 3;
    const int wn = wid >> 2;

    // ---- load A (precomputed fp16) + convert B (fp32 -> fp16) ----
    {
        const uint4* qh4 = reinterpret_cast<const uint4*>(g_qh);
        const float4* m4 = reinterpret_cast<const float4*>(mem);
#pragma unroll
        for (int it = 0; it < 4; it++) {
            int chunk = it * 512 + tid;      // 0..2047
            int r  = chunk >> 4;
            int c8 = chunk & 15;
            int c  = c8 * 8;
            int off = r * SSTRIDE + c;       // 16B-aligned (SSTRIDE*2 = 272 = 17*16)
            *reinterpret_cast<uint4*>(As + off) = qh4[(m0 + r) * 16 + c8];
            size_t bidx = ((size_t)(n0 + r) * K_DIM + c) >> 2;
            float4 f0 = m4[bidx];
            float4 f1 = m4[bidx + 1];
            uint4 vh;
            vh.x = pack2h(__float2half_rn(f0.x), __float2half_rn(f0.y));
            vh.y = pack2h(__float2half_rn(f0.z), __float2half_rn(f0.w));
            vh.z = pack2h(__float2half_rn(f1.x), __float2half_rn(f1.y));
            vh.w = pack2h(__float2half_rn(f1.z), __float2half_rn(f1.w));
            *reinterpret_cast<uint4*>(Bs + off) = vh;
        }
    }
    __syncthreads();

    // ---- mainloop: single fp16 product per k-step ----
    float acc[2][4][4];
#pragma unroll
    for (int mt = 0; mt < 2; mt++)
#pragma unroll
        for (int nt = 0; nt < 4; nt++)
#pragma unroll
            for (int j = 0; j < 4; j++) acc[mt][nt][j] = 0.0f;

    const int ar  = lid >> 2;
    const int akc = (lid & 3) * 2;

#pragma unroll
    for (int ks = 0; ks < 8; ks++) {
        const int k0 = ks * 16;
        uint32_t ah[2][4], bh[4][2];
#pragma unroll
        for (int mt = 0; mt < 2; mt++) {
            int rb = wm * 32 + mt * 16 + ar;
            ah[mt][0] = lds_b32(As, rb,     k0 + akc);
            ah[mt][1] = lds_b32(As, rb + 8, k0 + akc);
            ah[mt][2] = lds_b32(As, rb,     k0 + akc + 8);
            ah[mt][3] = lds_b32(As, rb + 8, k0 + akc + 8);
        }
#pragma unroll
        for (int nt = 0; nt < 4; nt++) {
            int nb = wn * 32 + nt * 8 + ar;
            bh[nt][0] = lds_b32(Bs, nb, k0 + akc);
            bh[nt][1] = lds_b32(Bs, nb, k0 + akc + 8);
        }
#pragma unroll
        for (int mt = 0; mt < 2; mt++)
#pragma unroll
            for (int nt = 0; nt < 4; nt++)
                mma_f16(acc[mt][nt], ah[mt], bh[nt]);
    }
    __syncthreads();     // operand smem dead; reuse as stage

    // ---- epilogue phase 1: exp -> SMEM stage (STS.64, conflict-free) ----
#pragma unroll
    for (int mt = 0; mt < 2; mt++) {
        const int lrow = wm * 32 + mt * 16 + ar;
        const int colw = wn * 32 + (lid & 3) * 2;
#pragma unroll
        for (int nt = 0; nt < 4; nt++) {
            float e00 = __expf(acc[mt][nt][0] * INV_T);
            float e01 = __expf(acc[mt][nt][1] * INV_T);
            float e10 = __expf(acc[mt][nt][2] * INV_T);
            float e11 = __expf(acc[mt][nt][3] * INV_T);
            float2* s0 = reinterpret_cast<float2*>(stage + lrow * STG_S + colw + nt * 8);
            float2* s1 = reinterpret_cast<float2*>(stage + (lrow + 8) * STG_S + colw + nt * 8);
            *s0 = make_float2(e00, e01);
            *s1 = make_float2(e10, e11);
        }
    }
    __syncthreads();

    // ---- epilogue phase 2: coalesced stores + row sums ----
    {
        const size_t obase = (size_t)m0 * LDOUT + 1 + n0;
#pragma unroll
        for (int rr = 0; rr < 8; rr++) {
            int row = wid * 8 + rr;
            float rsum = 0.0f;
#pragma unroll
            for (int j = 0; j < 4; j++) {
                float x = stage[row * STG_S + j * 32 + lid];
                out[obase + (size_t)row * LDOUT + j * 32 + lid] = x;
                rsum += x;
            }
#pragma unroll
            for (int o = 16; o > 0; o >>= 1)
                rsum += __shfl_down_sync(0xffffffffu, rsum, o);
            if (lid == 0) srows[row] = rsum;     // single writer
        }
    }
    __syncthreads();

    if (tid < 128) {
        float v = srows[tid];
        atomicAdd(&g_rowsum[m0 + tid], v);
#pragma unroll
        for (int o = 16; o > 0; o >>= 1) v += __shfl_down_sync(0xffffffffu, v, o);
        if (lid == 0) zw[tid >> 5] = v;
    }
    __syncthreads();
    if (tid == 0)
        g_Zpart[bid] = (double)(zw[0] + zw[1] + zw[2] + zw[3]);
}

// ---------------- l_pos + finalize (fused, single block) ----------------
__global__ void lpos_finalize_kernel(const float* __restrict__ q,
                                     const float* __restrict__ k,
                                     float* __restrict__ out,
                                     float* __restrict__ probs_out) {
    __shared__ double zs[8];
    __shared__ float ws[8];
    const int r = threadIdx.x;       // 256 threads
    const int v = r & 63;
    float acc = 0.0f;
#pragma unroll
    for (int c = 0; c < 4; c++) {
        int p = v + c * 64;
        if (p == r) continue;
        float s = 0.0f;
#pragma unroll 8
        for (int d = 0; d < K_DIM; d++)
            s = fmaf(q[(size_t)r * K_DIM + d], k[(size_t)p * K_DIM + d], s);
        acc += s;
    }
    float e = expf((acc * (1.0f / 3.0f)) * INV_T);
    out[(size_t)r * LDOUT] = e;

    float rowsum = g_rowsum[r] + e;
    float term = e / rowsum;
    double z = (double)e;
#pragma unroll
    for (int i = 0; i < 8; i++) z += g_Zpart[r + 256 * i];
#pragma unroll
    for (int o = 16; o > 0; o >>= 1) {
        z    += __shfl_down_sync(0xffffffffu, z, o);
        term += __shfl_down_sync(0xffffffffu, term, o);
    }
    if ((r & 31) == 0) { zs[r >> 5] = z; ws[r >> 5] = term; }
    __syncthreads();
    if (r == 0) {
        double zz = 0.0;
        float ts = 0.0f;
#pragma unroll
        for (int w = 0; w < 8; w++) { zz += zs[w]; ts += ws[w]; }
        probs_out[0] = ts / (float)NBS;
        double Z = zz / ((double)NBS * (double)LDOUT) * 1.0e6;
        g_invZ = (float)(1.0 / Z);
    }
}

// ---------------- tail: scale out by 1/Z ----------------
__global__ void scale_kernel(float4* __restrict__ out) {
    size_t i = (size_t)blockIdx.x * blockDim.x + threadIdx.x;
    const float inv = g_invZ;
    if (i < NOUT4) {
        float4 v = out[i];
        v.x *= inv; v.y *= inv; v.z *= inv; v.w *= inv;
        out[i] = v;
    }
}

extern "C" void kernel_launch(void* const* d_in, const int* in_sizes, int n_in,
                              void* d_out, int out_size) {
    const float* q   = (const float*)d_in[0];
    const float* k   = (const float*)d_in[1];
    const float* mem = (const float*)d_in[2];
    float* out = (float*)d_out;

    size_t mem_off = (size_t)out_size - (size_t)QK * K_DIM;
    float* newmem = out + mem_off;
    float* probs  = out + (mem_off - 1);

    cudaFuncSetAttribute(gemm_exp_kernel,
                         cudaFuncAttributeMaxDynamicSharedMemorySize, SMEM_BYTES);

    init_kernel<<<128, 256>>>(q);

    gemm_exp_kernel<<<NGEMM + NCOPY, 512, SMEM_BYTES>>>(mem, k, out, newmem);

    lpos_finalize_kernel<<<1, 256>>>(q, k, out, probs);

    scale_kernel<<<(unsigned)((NOUT4 + 255) / 256), 256>>>((float4*)out);
}